// round 6
// baseline (speedup 1.0000x reference)
#include <cuda_runtime.h>
#include <math.h>

// ---------------- problem constants ----------------
#define Hn     1024
#define DIN    2048
#define KEYD   1024
#define DICT   16384
#define A2CH   512
#define NACT   1024
#define Bn     256

// output layout (float32 elements)
#define OFF_A     0
#define OFF_PROB  256
#define OFF_V     512
#define OFF_ENT   768
#define OFF_HT    1024
#define OFF_CT    263168      // 1024 + 256*1024
#define OFF_BEST  525312
#define OFF_NK    525568
#define OFF_NV    17302784

// ---------------- scratch (device globals; no allocation) ----------------
__device__ float g_preact[Bn * 5 * Hn];          // 256x5120
__device__ float g_cpre[Bn * Hn];
__device__ float g_og[Bn * Hn];
__device__ float g_rg[Bn * Hn];
__device__ float g_invk[DICT];
__device__ float g_invq[Bn];
__device__ unsigned long long g_best[Bn];
__device__ float g_ha_part[4 * Bn * A2CH];       // k-split partials (deterministic)
__device__ float g_ha[Bn * A2CH];
__device__ float g_logit_part[2 * Bn * NACT];

// ---------------- helpers ----------------
__device__ __forceinline__ unsigned long long pack_max(float v, int idx) {
    unsigned u = __float_as_uint(v);
    u = (u & 0x80000000u) ? ~u : (u | 0x80000000u);       // order-preserving encode
    return ((unsigned long long)u << 32) | (unsigned)(0xFFFFFFFFu - (unsigned)idx); // tie -> lowest idx
}
__device__ __forceinline__ int unpack_idx(unsigned long long p) {
    return (int)(0xFFFFFFFFu - (unsigned)(p & 0xFFFFFFFFull));
}
__device__ __forceinline__ float sigmoidf_(float x) { return 1.0f / (1.0f + expf(-x)); }

// threefry2x32, key = (0,1)  (jax.random.key(1)), PARTITIONABLE counter scheme
// (modern JAX default: jax_threefry_partitionable=True):
//   per flat element i: block input (x0, x1) = (hi32(i), lo32(i)) = (0, i),
//   32-bit draw = out_x0 ^ out_x1.
__device__ __forceinline__ float gumbel_noise(unsigned idx) {
    unsigned x0 = 0u, x1 = idx;
    const unsigned ks0 = 0u, ks1 = 1u, ks2 = 0x1BD11BDBu; // 0^1^0x1BD11BDA
    x0 += ks0; x1 += ks1;
#define TFR(d) { x0 += x1; x1 = (x1 << (d)) | (x1 >> (32 - (d))); x1 ^= x0; }
    TFR(13) TFR(15) TFR(26) TFR(6)   x0 += ks1; x1 += ks2 + 1u;
    TFR(17) TFR(29) TFR(16) TFR(24)  x0 += ks2; x1 += ks0 + 2u;
    TFR(13) TFR(15) TFR(26) TFR(6)   x0 += ks0; x1 += ks1 + 3u;
    TFR(17) TFR(29) TFR(16) TFR(24)  x0 += ks1; x1 += ks2 + 4u;
    TFR(13) TFR(15) TFR(26) TFR(6)   x0 += ks2; x1 += ks0 + 5u;
#undef TFR
    unsigned bits = x0 ^ x1;
    float f = __uint_as_float((bits >> 9) | 0x3f800000u) - 1.0f;
    const float TINY = 1.17549435e-38f;
    float u = fmaxf(f + TINY, TINY);
    return -logf(-logf(u));
}

// ---------------- kernel 1: preact GEMM  (256 x 5120, K = 2048 then 1024) ----------------
__global__ __launch_bounds__(256) void gemm1_kernel(
    const float* __restrict__ obs, const float* __restrict__ hin,
    const float* __restrict__ Wi,  const float* __restrict__ Wh,
    const float* __restrict__ bi,  const float* __restrict__ bh)
{
    __shared__ float As[16][64];
    __shared__ float Bs[16][128];
    int tid = threadIdx.x;
    int tx = tid & 15, ty = tid >> 4;
    int m_blk = blockIdx.y * 64;
    int n_blk = blockIdx.x * 128;
    float acc[4][8];
#pragma unroll
    for (int i = 0; i < 4; i++)
#pragma unroll
        for (int j = 0; j < 8; j++) acc[i][j] = 0.f;

    for (int seg = 0; seg < 2; seg++) {
        const float* A  = seg ? hin : obs;
        const float* Bw = seg ? Wh  : Wi;
        int K = seg ? Hn : DIN;
        for (int k0 = 0; k0 < K; k0 += 16) {
            {   int r = tid >> 2, kk = (tid & 3) * 4;
                float4 av = *reinterpret_cast<const float4*>(&A[(m_blk + r) * K + k0 + kk]);
                As[kk + 0][r] = av.x; As[kk + 1][r] = av.y;
                As[kk + 2][r] = av.z; As[kk + 3][r] = av.w; }
            {   int r = tid >> 5, c = (tid & 31) * 4;
                *reinterpret_cast<float4*>(&Bs[r][c]) =
                    *reinterpret_cast<const float4*>(&Bw[(k0 + r) * 5120 + n_blk + c]);
                *reinterpret_cast<float4*>(&Bs[r + 8][c]) =
                    *reinterpret_cast<const float4*>(&Bw[(k0 + r + 8) * 5120 + n_blk + c]); }
            __syncthreads();
#pragma unroll
            for (int k = 0; k < 16; k++) {
                float4 a4 = *reinterpret_cast<const float4*>(&As[k][ty * 4]);
                float4 b0 = *reinterpret_cast<const float4*>(&Bs[k][tx * 8]);
                float4 b1 = *reinterpret_cast<const float4*>(&Bs[k][tx * 8 + 4]);
                float a[4]  = {a4.x, a4.y, a4.z, a4.w};
                float bv[8] = {b0.x, b0.y, b0.z, b0.w, b1.x, b1.y, b1.z, b1.w};
#pragma unroll
                for (int i = 0; i < 4; i++)
#pragma unroll
                    for (int j = 0; j < 8; j++) acc[i][j] = fmaf(a[i], bv[j], acc[i][j]);
            }
            __syncthreads();
        }
    }
#pragma unroll
    for (int i = 0; i < 4; i++) {
        int m = m_blk + ty * 4 + i;
#pragma unroll
        for (int j = 0; j < 8; j++) {
            int n = n_blk + tx * 8 + j;
            g_preact[m * 5120 + n] = acc[i][j] + bi[n] + bh[n];
        }
    }
}

// ---------------- kernel 2: mem_keys norm + copy to new_keys ----------------
__global__ __launch_bounds__(256) void keys_norm_copy(const float4* __restrict__ mk,
                                                      float4* __restrict__ nk)
{
    int warp = threadIdx.x >> 5, lane = threadIdx.x & 31;
    int row = blockIdx.x * 8 + warp;
    const float4* src = mk + (size_t)row * 256;
    float4* dst = nk + (size_t)row * 256;
    float s = 0.f;
#pragma unroll
    for (int i = 0; i < 8; i++) {
        float4 v = src[i * 32 + lane];
        dst[i * 32 + lane] = v;
        s += v.x * v.x + v.y * v.y + v.z * v.z + v.w * v.w;
    }
#pragma unroll
    for (int o = 16; o; o >>= 1) s += __shfl_xor_sync(0xffffffffu, s, o);
    if (lane == 0) g_invk[row] = 1.0f / fmaxf(sqrtf(s), 1e-8f);
}

// ---------------- kernel 3: plain copy mem_vals -> new_vals ----------------
__global__ __launch_bounds__(256) void copy_vals(const float4* __restrict__ src,
                                                 float4* __restrict__ dst)
{
    int i = blockIdx.x * 256 + threadIdx.x;
    dst[i] = src[i];
}

// ---------------- kernel 4: q norm + init best ----------------
__global__ __launch_bounds__(256) void qnorm_init(const float4* __restrict__ q)
{
    int warp = threadIdx.x >> 5, lane = threadIdx.x & 31;
    int row = blockIdx.x * 8 + warp;
    const float4* src = q + (size_t)row * 256;
    float s = 0.f;
#pragma unroll
    for (int i = 0; i < 8; i++) {
        float4 v = src[i * 32 + lane];
        s += v.x * v.x + v.y * v.y + v.z * v.z + v.w * v.w;
    }
#pragma unroll
    for (int o = 16; o; o >>= 1) s += __shfl_xor_sync(0xffffffffu, s, o);
    if (lane == 0) g_invq[row] = 1.0f / fmaxf(sqrtf(s), 1e-8f);
    if (blockIdx.x == 0) g_best[threadIdx.x] = 0ull;
}

// ---------------- kernel 5: gates ----------------
__global__ __launch_bounds__(256) void gates_kernel(const float* __restrict__ c)
{
    int idx = blockIdx.x * 256 + threadIdx.x;   // 262144
    int b = idx >> 10, j = idx & 1023;
    const float* pr = g_preact + b * 5120;
    float f  = sigmoidf_(pr[j]);
    float it = sigmoidf_(pr[1024 + j]);
    float o  = sigmoidf_(pr[2048 + j]);
    float r  = sigmoidf_(pr[3072 + j]);
    float cn = tanhf(pr[4096 + j]);
    g_cpre[idx] = f * c[idx] + it * cn;
    g_og[idx] = o;
    g_rg[idx] = r;
}

// ---------------- kernel 6: sims GEMM + fused argmax ----------------
// M = dict rows (64/blk), N = batch (128/blk), K = 1024
__global__ __launch_bounds__(256) void sims_kernel(const float* __restrict__ mk,
                                                   const float* __restrict__ q)
{
    __shared__ float As[16][64];
    __shared__ float Bs[16][128];
    __shared__ unsigned long long sm[128];
    int tid = threadIdx.x;
    int tx = tid & 15, ty = tid >> 4;
    int m_blk = blockIdx.x * 64;      // dict
    int n_blk = blockIdx.y * 128;     // batch
    float acc[4][8];
#pragma unroll
    for (int i = 0; i < 4; i++)
#pragma unroll
        for (int j = 0; j < 8; j++) acc[i][j] = 0.f;

    for (int k0 = 0; k0 < KEYD; k0 += 16) {
        {   int r = tid >> 2, kk = (tid & 3) * 4;
            float4 av = *reinterpret_cast<const float4*>(&mk[(size_t)(m_blk + r) * KEYD + k0 + kk]);
            As[kk + 0][r] = av.x; As[kk + 1][r] = av.y;
            As[kk + 2][r] = av.z; As[kk + 3][r] = av.w; }
        {   int bl = tid >> 1, kk = (tid & 1) * 8;
            float4 v0 = *reinterpret_cast<const float4*>(&q[(n_blk + bl) * KEYD + k0 + kk]);
            float4 v1 = *reinterpret_cast<const float4*>(&q[(n_blk + bl) * KEYD + k0 + kk + 4]);
            Bs[kk + 0][bl] = v0.x; Bs[kk + 1][bl] = v0.y; Bs[kk + 2][bl] = v0.z; Bs[kk + 3][bl] = v0.w;
            Bs[kk + 4][bl] = v1.x; Bs[kk + 5][bl] = v1.y; Bs[kk + 6][bl] = v1.z; Bs[kk + 7][bl] = v1.w; }
        __syncthreads();
#pragma unroll
        for (int k = 0; k < 16; k++) {
            float4 a4 = *reinterpret_cast<const float4*>(&As[k][ty * 4]);
            float4 b0 = *reinterpret_cast<const float4*>(&Bs[k][tx * 8]);
            float4 b1 = *reinterpret_cast<const float4*>(&Bs[k][tx * 8 + 4]);
            float a[4]  = {a4.x, a4.y, a4.z, a4.w};
            float bv[8] = {b0.x, b0.y, b0.z, b0.w, b1.x, b1.y, b1.z, b1.w};
#pragma unroll
            for (int i = 0; i < 4; i++)
#pragma unroll
                for (int j = 0; j < 8; j++) acc[i][j] = fmaf(a[i], bv[j], acc[i][j]);
        }
        __syncthreads();
    }
    // fused argmax epilogue
    if (ty == 0) {
#pragma unroll
        for (int j = 0; j < 8; j++) sm[tx * 8 + j] = 0ull;
    }
    __syncthreads();
    float iq[8];
#pragma unroll
    for (int j = 0; j < 8; j++) iq[j] = g_invq[n_blk + tx * 8 + j];
#pragma unroll
    for (int i = 0; i < 4; i++) {
        int d = m_blk + ty * 4 + i;
        float ik = g_invk[d];
#pragma unroll
        for (int j = 0; j < 8; j++) {
            float v = acc[i][j] * ik * iq[j];
            atomicMax(&sm[tx * 8 + j], pack_max(v, d));
        }
    }
    __syncthreads();
    if (ty == 0) {
#pragma unroll
        for (int j = 0; j < 8; j++)
            atomicMax(&g_best[n_blk + tx * 8 + j], sm[tx * 8 + j]);
    }
}

// ---------------- kernel 7: finalize c_t, h_t, best_mem_id ----------------
__global__ __launch_bounds__(256) void finalize_kernel(const float* __restrict__ mem_vals,
                                                       float* __restrict__ out)
{
    int b = blockIdx.x;
    int best = unpack_idx(g_best[b]);
    const float* mv = mem_vals + (size_t)best * Hn;
    for (int j = threadIdx.x; j < Hn; j += 256) {
        float m = tanhf(mv[j]);
        float ct = g_cpre[b * Hn + j] + g_rg[b * Hn + j] * m;
        float ht = g_og[b * Hn + j] * tanhf(ct);
        out[OFF_CT + b * Hn + j] = ct;
        out[OFF_HT + b * Hn + j] = ht;
    }
    if (threadIdx.x == 0) out[OFF_BEST + b] = (float)best;
}

// ---------------- kernel 8: ha = relu(ct @ Wa + ba), k-split partials ----------------
__global__ __launch_bounds__(256) void gemm_ha_kernel(const float* __restrict__ A,
                                                      const float* __restrict__ Bw)
{
    __shared__ float As[16][64];
    __shared__ float Bs[16][64];
    int tid = threadIdx.x, tx = tid & 15, ty = tid >> 4;
    int m_blk = blockIdx.y * 64, n_blk = blockIdx.x * 64, kz = blockIdx.z;
    float acc[4][4];
#pragma unroll
    for (int i = 0; i < 4; i++)
#pragma unroll
        for (int j = 0; j < 4; j++) acc[i][j] = 0.f;
    int kbeg = kz * 256;
    for (int k0 = kbeg; k0 < kbeg + 256; k0 += 16) {
        {   int r = tid >> 2, kk = (tid & 3) * 4;
            float4 av = *reinterpret_cast<const float4*>(&A[(m_blk + r) * Hn + k0 + kk]);
            As[kk + 0][r] = av.x; As[kk + 1][r] = av.y;
            As[kk + 2][r] = av.z; As[kk + 3][r] = av.w; }
        {   int r = tid >> 4, cc = (tid & 15) * 4;
            *reinterpret_cast<float4*>(&Bs[r][cc]) =
                *reinterpret_cast<const float4*>(&Bw[(k0 + r) * A2CH + n_blk + cc]); }
        __syncthreads();
#pragma unroll
        for (int k = 0; k < 16; k++) {
            float4 a4 = *reinterpret_cast<const float4*>(&As[k][ty * 4]);
            float4 b4 = *reinterpret_cast<const float4*>(&Bs[k][tx * 4]);
            float a[4]  = {a4.x, a4.y, a4.z, a4.w};
            float bv[4] = {b4.x, b4.y, b4.z, b4.w};
#pragma unroll
            for (int i = 0; i < 4; i++)
#pragma unroll
                for (int j = 0; j < 4; j++) acc[i][j] = fmaf(a[i], bv[j], acc[i][j]);
        }
        __syncthreads();
    }
    float* C = g_ha_part + kz * (Bn * A2CH);
#pragma unroll
    for (int i = 0; i < 4; i++)
#pragma unroll
        for (int j = 0; j < 4; j++)
            C[(m_blk + ty * 4 + i) * A2CH + n_blk + tx * 4 + j] = acc[i][j];
}

__global__ __launch_bounds__(256) void relu_ha_kernel(const float* __restrict__ ba)
{
    int idx = blockIdx.x * 256 + threadIdx.x;   // 131072
    float s = g_ha_part[idx] + g_ha_part[131072 + idx] + g_ha_part[262144 + idx]
            + g_ha_part[393216 + idx] + ba[idx & 511];
    g_ha[idx] = fmaxf(s, 0.f);
}

// ---------------- kernel 9: logits partials ----------------
__global__ __launch_bounds__(256) void gemm_logits_kernel(const float* __restrict__ Bw)
{
    __shared__ float As[16][64];
    __shared__ float Bs[16][64];
    int tid = threadIdx.x, tx = tid & 15, ty = tid >> 4;
    int m_blk = blockIdx.y * 64, n_blk = blockIdx.x * 64, kz = blockIdx.z;
    float acc[4][4];
#pragma unroll
    for (int i = 0; i < 4; i++)
#pragma unroll
        for (int j = 0; j < 4; j++) acc[i][j] = 0.f;
    int kbeg = kz * 256;
    for (int k0 = kbeg; k0 < kbeg + 256; k0 += 16) {
        {   int r = tid >> 2, kk = (tid & 3) * 4;
            float4 av = *reinterpret_cast<const float4*>(&g_ha[(m_blk + r) * A2CH + k0 + kk]);
            As[kk + 0][r] = av.x; As[kk + 1][r] = av.y;
            As[kk + 2][r] = av.z; As[kk + 3][r] = av.w; }
        {   int r = tid >> 4, cc = (tid & 15) * 4;
            *reinterpret_cast<float4*>(&Bs[r][cc]) =
                *reinterpret_cast<const float4*>(&Bw[(k0 + r) * NACT + n_blk + cc]); }
        __syncthreads();
#pragma unroll
        for (int k = 0; k < 16; k++) {
            float4 a4 = *reinterpret_cast<const float4*>(&As[k][ty * 4]);
            float4 b4 = *reinterpret_cast<const float4*>(&Bs[k][tx * 4]);
            float a[4]  = {a4.x, a4.y, a4.z, a4.w};
            float bv[4] = {b4.x, b4.y, b4.z, b4.w};
#pragma unroll
            for (int i = 0; i < 4; i++)
#pragma unroll
                for (int j = 0; j < 4; j++) acc[i][j] = fmaf(a[i], bv[j], acc[i][j]);
        }
        __syncthreads();
    }
    float* C = g_logit_part + kz * (Bn * NACT);
#pragma unroll
    for (int i = 0; i < 4; i++)
#pragma unroll
        for (int j = 0; j < 4; j++)
            C[(m_blk + ty * 4 + i) * NACT + n_blk + tx * 4 + j] = acc[i][j];
}

// ---------------- kernel 10: softmax / entropy / categorical / value head ----------------
__global__ __launch_bounds__(256) void head_kernel(const float* __restrict__ b_actor,
                                                   const float* __restrict__ Wc,
                                                   const float* __restrict__ bc,
                                                   float* __restrict__ out)
{
    int b = blockIdx.x, tid = threadIdx.x;
    __shared__ float sl[NACT];
    __shared__ float red[256];
    __shared__ unsigned long long redp[256];

    float lmax = -1e30f;
#pragma unroll
    for (int t = 0; t < 4; t++) {
        int j = tid + t * 256;
        float v = g_logit_part[b * NACT + j] + g_logit_part[Bn * NACT + b * NACT + j] + b_actor[j];
        sl[j] = v;
        lmax = fmaxf(lmax, v);
    }
    red[tid] = lmax; __syncthreads();
    for (int s = 128; s > 0; s >>= 1) { if (tid < s) red[tid] = fmaxf(red[tid], red[tid + s]); __syncthreads(); }
    float mx = red[0]; __syncthreads();

    float lsum = 0.f;
#pragma unroll
    for (int t = 0; t < 4; t++) lsum += expf(sl[tid + t * 256] - mx);
    red[tid] = lsum; __syncthreads();
    for (int s = 128; s > 0; s >>= 1) { if (tid < s) red[tid] += red[tid + s]; __syncthreads(); }
    float logZ = logf(red[0]); __syncthreads();

    float ent = 0.f;
    unsigned long long bp = 0ull;
#pragma unroll
    for (int t = 0; t < 4; t++) {
        int j = tid + t * 256;
        float lp = sl[j] - mx - logZ;
        sl[j] = lp;
        ent -= expf(lp) * lp;
        float g = gumbel_noise((unsigned)(b * NACT + j));
        unsigned long long pk = pack_max(lp + g, j);
        bp = (bp > pk) ? bp : pk;
    }
    red[tid] = ent; redp[tid] = bp; __syncthreads();
    for (int s = 128; s > 0; s >>= 1) {
        if (tid < s) {
            red[tid] += red[tid + s];
            unsigned long long o = redp[tid + s];
            if (o > redp[tid]) redp[tid] = o;
        }
        __syncthreads();
    }
    float entropy = red[0];
    unsigned long long bpf = redp[0];
    __syncthreads();

    float vv = g_ha[b * A2CH + tid] * Wc[tid] + g_ha[b * A2CH + 256 + tid] * Wc[256 + tid];
    red[tid] = vv; __syncthreads();
    for (int s = 128; s > 0; s >>= 1) { if (tid < s) red[tid] += red[tid + s]; __syncthreads(); }

    if (tid == 0) {
        int a = unpack_idx(bpf);
        out[OFF_A + b]    = (float)a;
        out[OFF_PROB + b] = sl[a];
        out[OFF_V + b]    = red[0] + bc[0];
        out[OFF_ENT + b]  = entropy;
    }
}

// ---------------- kernel 11: scatter writes (last-wins, XLA order) ----------------
__global__ __launch_bounds__(256) void scatter_kernel(const int* __restrict__ widx,
                                                      const float* __restrict__ q,
                                                      const float* __restrict__ ct,
                                                      float* __restrict__ nk,
                                                      float* __restrict__ nv)
{
    int b = blockIdx.x;
    __shared__ int win;
    if (threadIdx.x == 0) {
        int idx = widx[b];
        int w = 1;
        for (int bp = b + 1; bp < Bn; bp++)
            if (widx[bp] == idx) { w = 0; break; }
        win = w;
    }
    __syncthreads();
    if (!win) return;
    int row = widx[b];
    for (int j = threadIdx.x; j < KEYD; j += 256) {
        nk[(size_t)row * KEYD + j] = q[b * KEYD + j];
        nv[(size_t)row * Hn + j]   = ct[b * Hn + j];
    }
}

// ---------------- launch ----------------
extern "C" void kernel_launch(void* const* d_in, const int* in_sizes, int n_in,
                              void* d_out, int out_size)
{
    const float* obs      = (const float*)d_in[0];
    const float* barcode  = (const float*)d_in[1];
    const float* hin      = (const float*)d_in[2];
    const float* cin      = (const float*)d_in[3];
    const int*   widx     = (const int*)d_in[4];
    const float* Wi       = (const float*)d_in[5];
    const float* bi       = (const float*)d_in[6];
    const float* Wh       = (const float*)d_in[7];
    const float* bh       = (const float*)d_in[8];
    const float* mem_keys = (const float*)d_in[9];
    const float* mem_vals = (const float*)d_in[10];
    const float* Wa       = (const float*)d_in[11];
    const float* ba       = (const float*)d_in[12];
    const float* W_actor  = (const float*)d_in[13];
    const float* b_actor  = (const float*)d_in[14];
    const float* W_critic = (const float*)d_in[15];
    const float* b_critic = (const float*)d_in[16];
    float* out = (float*)d_out;

    gemm1_kernel<<<dim3(40, 4), 256>>>(obs, hin, Wi, Wh, bi, bh);
    keys_norm_copy<<<2048, 256>>>((const float4*)mem_keys, (float4*)(out + OFF_NK));
    copy_vals<<<16384, 256>>>((const float4*)mem_vals, (float4*)(out + OFF_NV));
    qnorm_init<<<32, 256>>>((const float4*)barcode);
    gates_kernel<<<1024, 256>>>(cin);
    sims_kernel<<<dim3(256, 2), 256>>>(mem_keys, barcode);
    finalize_kernel<<<256, 256>>>(mem_vals, out);
    gemm_ha_kernel<<<dim3(8, 4, 4), 256>>>(out + OFF_CT, Wa);
    relu_ha_kernel<<<512, 256>>>(ba);
    gemm_logits_kernel<<<dim3(16, 4, 2), 256>>>(W_actor);
    head_kernel<<<256, 256>>>(b_actor, W_critic, b_critic, out);
    scatter_kernel<<<256, 256>>>(widx, barcode, out + OFF_CT, out + OFF_NK, out + OFF_NV);
}

// round 7
// speedup vs baseline: 1.0583x; 1.0583x over previous
#include <cuda_runtime.h>
#include <math.h>

// ---------------- problem constants ----------------
#define Hn     1024
#define DIN    2048
#define KEYD   1024
#define DICT   16384
#define A2CH   512
#define NACT   1024
#define Bn     256

// output layout (float32 elements)
#define OFF_A     0
#define OFF_PROB  256
#define OFF_V     512
#define OFF_ENT   768
#define OFF_HT    1024
#define OFF_CT    263168      // 1024 + 256*1024
#define OFF_BEST  525312
#define OFF_NK    525568
#define OFF_NV    17302784

// ---------------- scratch (device globals; no allocation) ----------------
__device__ float g_preact[Bn * 5 * Hn];          // 256x5120
__device__ float g_cpre[Bn * Hn];
__device__ float g_og[Bn * Hn];
__device__ float g_rg[Bn * Hn];
__device__ float g_invk[DICT];
__device__ float g_invq[Bn];
__device__ unsigned long long g_best[Bn];
__device__ float g_ha_part[4 * Bn * A2CH];       // k-split partials (deterministic)
__device__ float g_ha[Bn * A2CH];
__device__ float g_logit_part[2 * Bn * NACT];

// ---------------- helpers ----------------
__device__ __forceinline__ unsigned long long pack_max(float v, int idx) {
    unsigned u = __float_as_uint(v);
    u = (u & 0x80000000u) ? ~u : (u | 0x80000000u);       // order-preserving encode
    return ((unsigned long long)u << 32) | (unsigned)(0xFFFFFFFFu - (unsigned)idx); // tie -> lowest idx
}
__device__ __forceinline__ int unpack_idx(unsigned long long p) {
    return (int)(0xFFFFFFFFu - (unsigned)(p & 0xFFFFFFFFull));
}
__device__ __forceinline__ float sigmoidf_(float x) { return 1.0f / (1.0f + expf(-x)); }

// threefry2x32, key = (0,1), PARTITIONABLE counter scheme (modern JAX default):
//   per flat element i: block input (x0, x1) = (hi32(i), lo32(i)) = (0, i),
//   32-bit draw = out_x0 ^ out_x1.
__device__ __forceinline__ float gumbel_noise(unsigned idx) {
    unsigned x0 = 0u, x1 = idx;
    const unsigned ks0 = 0u, ks1 = 1u, ks2 = 0x1BD11BDBu; // 0^1^0x1BD11BDA
    x0 += ks0; x1 += ks1;
#define TFR(d) { x0 += x1; x1 = (x1 << (d)) | (x1 >> (32 - (d))); x1 ^= x0; }
    TFR(13) TFR(15) TFR(26) TFR(6)   x0 += ks1; x1 += ks2 + 1u;
    TFR(17) TFR(29) TFR(16) TFR(24)  x0 += ks2; x1 += ks0 + 2u;
    TFR(13) TFR(15) TFR(26) TFR(6)   x0 += ks0; x1 += ks1 + 3u;
    TFR(17) TFR(29) TFR(16) TFR(24)  x0 += ks1; x1 += ks2 + 4u;
    TFR(13) TFR(15) TFR(26) TFR(6)   x0 += ks2; x1 += ks0 + 5u;
#undef TFR
    unsigned bits = x0 ^ x1;
    float f = __uint_as_float((bits >> 9) | 0x3f800000u) - 1.0f;
    const float TINY = 1.17549435e-38f;
    float u = fmaxf(f + TINY, TINY);
    return -logf(-logf(u));
}

// ---------------- kernel 1: preact GEMM  (256 x 5120, K = 2048 then 1024) ----------------
// double-buffered smem, register-staged prefetch, one sync per k-tile
__global__ __launch_bounds__(256) void gemm1_kernel(
    const float* __restrict__ obs, const float* __restrict__ hin,
    const float* __restrict__ Wi,  const float* __restrict__ Wh,
    const float* __restrict__ bi,  const float* __restrict__ bh)
{
    __shared__ float As[2][16][64];
    __shared__ float Bs[2][16][128];
    int tid = threadIdx.x;
    int tx = tid & 15, ty = tid >> 4;
    int m_blk = blockIdx.y * 64;
    int n_blk = blockIdx.x * 128;
    int ar = tid >> 2, akk = (tid & 3) * 4;   // A stage: 64 rows x 16 k
    int br = tid >> 5, bc = (tid & 31) * 4;   // B stage: rows br, br+8 x 128 n

    float4 sa, sb0, sb1;
    auto load_stage = [&](int t) {
        const float* A; const float* Bw; int K, k0;
        if (t < 128) { A = obs; Bw = Wi; K = DIN; k0 = t * 16; }
        else         { A = hin; Bw = Wh; K = Hn;  k0 = (t - 128) * 16; }
        sa  = *reinterpret_cast<const float4*>(&A[(m_blk + ar) * K + k0 + akk]);
        sb0 = *reinterpret_cast<const float4*>(&Bw[(k0 + br) * 5120 + n_blk + bc]);
        sb1 = *reinterpret_cast<const float4*>(&Bw[(k0 + br + 8) * 5120 + n_blk + bc]);
    };
    auto store_stage = [&](int buf) {
        As[buf][akk + 0][ar] = sa.x; As[buf][akk + 1][ar] = sa.y;
        As[buf][akk + 2][ar] = sa.z; As[buf][akk + 3][ar] = sa.w;
        *reinterpret_cast<float4*>(&Bs[buf][br][bc])     = sb0;
        *reinterpret_cast<float4*>(&Bs[buf][br + 8][bc]) = sb1;
    };

    float acc[4][8];
#pragma unroll
    for (int i = 0; i < 4; i++)
#pragma unroll
        for (int j = 0; j < 8; j++) acc[i][j] = 0.f;

    load_stage(0); store_stage(0); __syncthreads();
    const int T = 192;   // 128 (DIN) + 64 (Hn) k-tiles
    for (int t = 0; t < T; t++) {
        int cur = t & 1;
        if (t + 1 < T) load_stage(t + 1);
#pragma unroll
        for (int k = 0; k < 16; k++) {
            float4 a4 = *reinterpret_cast<const float4*>(&As[cur][k][ty * 4]);
            float4 b0 = *reinterpret_cast<const float4*>(&Bs[cur][k][tx * 8]);
            float4 b1 = *reinterpret_cast<const float4*>(&Bs[cur][k][tx * 8 + 4]);
            float a[4]  = {a4.x, a4.y, a4.z, a4.w};
            float bv[8] = {b0.x, b0.y, b0.z, b0.w, b1.x, b1.y, b1.z, b1.w};
#pragma unroll
            for (int i = 0; i < 4; i++)
#pragma unroll
                for (int j = 0; j < 8; j++) acc[i][j] = fmaf(a[i], bv[j], acc[i][j]);
        }
        if (t + 1 < T) { store_stage(cur ^ 1); __syncthreads(); }
    }
#pragma unroll
    for (int i = 0; i < 4; i++) {
        int m = m_blk + ty * 4 + i;
#pragma unroll
        for (int j = 0; j < 8; j++) {
            int n = n_blk + tx * 8 + j;
            g_preact[m * 5120 + n] = acc[i][j] + bi[n] + bh[n];
        }
    }
}

// ---------------- kernel 2: mem_keys norm + copy to new_keys ----------------
__global__ __launch_bounds__(256) void keys_norm_copy(const float4* __restrict__ mk,
                                                      float4* __restrict__ nk)
{
    int warp = threadIdx.x >> 5, lane = threadIdx.x & 31;
    int row = blockIdx.x * 8 + warp;
    const float4* src = mk + (size_t)row * 256;
    float4* dst = nk + (size_t)row * 256;
    float s = 0.f;
#pragma unroll
    for (int i = 0; i < 8; i++) {
        float4 v = src[i * 32 + lane];
        dst[i * 32 + lane] = v;
        s += v.x * v.x + v.y * v.y + v.z * v.z + v.w * v.w;
    }
#pragma unroll
    for (int o = 16; o; o >>= 1) s += __shfl_xor_sync(0xffffffffu, s, o);
    if (lane == 0) g_invk[row] = 1.0f / fmaxf(sqrtf(s), 1e-8f);
}

// ---------------- kernel 3: plain copy mem_vals -> new_vals ----------------
__global__ __launch_bounds__(256) void copy_vals(const float4* __restrict__ src,
                                                 float4* __restrict__ dst)
{
    int i = blockIdx.x * 256 + threadIdx.x;
    dst[i] = src[i];
}

// ---------------- kernel 4: q norm + init best ----------------
__global__ __launch_bounds__(256) void qnorm_init(const float4* __restrict__ q)
{
    int warp = threadIdx.x >> 5, lane = threadIdx.x & 31;
    int row = blockIdx.x * 8 + warp;
    const float4* src = q + (size_t)row * 256;
    float s = 0.f;
#pragma unroll
    for (int i = 0; i < 8; i++) {
        float4 v = src[i * 32 + lane];
        s += v.x * v.x + v.y * v.y + v.z * v.z + v.w * v.w;
    }
#pragma unroll
    for (int o = 16; o; o >>= 1) s += __shfl_xor_sync(0xffffffffu, s, o);
    if (lane == 0) g_invq[row] = 1.0f / fmaxf(sqrtf(s), 1e-8f);
    if (blockIdx.x == 0) g_best[threadIdx.x] = 0ull;
}

// ---------------- kernel 5: gates ----------------
__global__ __launch_bounds__(256) void gates_kernel(const float* __restrict__ c)
{
    int idx = blockIdx.x * 256 + threadIdx.x;   // 262144
    int b = idx >> 10, j = idx & 1023;
    const float* pr = g_preact + b * 5120;
    float f  = sigmoidf_(pr[j]);
    float it = sigmoidf_(pr[1024 + j]);
    float o  = sigmoidf_(pr[2048 + j]);
    float r  = sigmoidf_(pr[3072 + j]);
    float cn = tanhf(pr[4096 + j]);
    g_cpre[idx] = f * c[idx] + it * cn;
    g_og[idx] = o;
    g_rg[idx] = r;
}

// ---------------- kernel 6: sims GEMM + fused argmax ----------------
// M = dict rows (64/blk), N = batch (128/blk), K = 1024; double-buffered
__global__ __launch_bounds__(256) void sims_kernel(const float* __restrict__ mk,
                                                   const float* __restrict__ q)
{
    __shared__ float As[2][16][64];
    __shared__ float Bs[2][16][128];
    __shared__ unsigned long long sm[128];
    int tid = threadIdx.x;
    int tx = tid & 15, ty = tid >> 4;
    int m_blk = blockIdx.x * 64;      // dict
    int n_blk = blockIdx.y * 128;     // batch
    int ar = tid >> 2, akk = (tid & 3) * 4;   // A stage
    int qbl = tid >> 1, qkk = (tid & 1) * 8;  // q stage: 128 batch x 16 k

    float4 sa, sq0, sq1;
    auto load_stage = [&](int t) {
        int k0 = t * 16;
        sa  = *reinterpret_cast<const float4*>(&mk[(size_t)(m_blk + ar) * KEYD + k0 + akk]);
        sq0 = *reinterpret_cast<const float4*>(&q[(n_blk + qbl) * KEYD + k0 + qkk]);
        sq1 = *reinterpret_cast<const float4*>(&q[(n_blk + qbl) * KEYD + k0 + qkk + 4]);
    };
    auto store_stage = [&](int buf) {
        As[buf][akk + 0][ar] = sa.x; As[buf][akk + 1][ar] = sa.y;
        As[buf][akk + 2][ar] = sa.z; As[buf][akk + 3][ar] = sa.w;
        Bs[buf][qkk + 0][qbl] = sq0.x; Bs[buf][qkk + 1][qbl] = sq0.y;
        Bs[buf][qkk + 2][qbl] = sq0.z; Bs[buf][qkk + 3][qbl] = sq0.w;
        Bs[buf][qkk + 4][qbl] = sq1.x; Bs[buf][qkk + 5][qbl] = sq1.y;
        Bs[buf][qkk + 6][qbl] = sq1.z; Bs[buf][qkk + 7][qbl] = sq1.w;
    };

    float acc[4][8];
#pragma unroll
    for (int i = 0; i < 4; i++)
#pragma unroll
        for (int j = 0; j < 8; j++) acc[i][j] = 0.f;

    load_stage(0); store_stage(0); __syncthreads();
    const int T = KEYD / 16;   // 64
    for (int t = 0; t < T; t++) {
        int cur = t & 1;
        if (t + 1 < T) load_stage(t + 1);
#pragma unroll
        for (int k = 0; k < 16; k++) {
            float4 a4 = *reinterpret_cast<const float4*>(&As[cur][k][ty * 4]);
            float4 b0 = *reinterpret_cast<const float4*>(&Bs[cur][k][tx * 8]);
            float4 b1 = *reinterpret_cast<const float4*>(&Bs[cur][k][tx * 8 + 4]);
            float a[4]  = {a4.x, a4.y, a4.z, a4.w};
            float bv[8] = {b0.x, b0.y, b0.z, b0.w, b1.x, b1.y, b1.z, b1.w};
#pragma unroll
            for (int i = 0; i < 4; i++)
#pragma unroll
                for (int j = 0; j < 8; j++) acc[i][j] = fmaf(a[i], bv[j], acc[i][j]);
        }
        if (t + 1 < T) { store_stage(cur ^ 1); __syncthreads(); }
    }
    // fused argmax epilogue
    __syncthreads();
    if (ty == 0) {
#pragma unroll
        for (int j = 0; j < 8; j++) sm[tx * 8 + j] = 0ull;
    }
    __syncthreads();
    float iq[8];
#pragma unroll
    for (int j = 0; j < 8; j++) iq[j] = g_invq[n_blk + tx * 8 + j];
#pragma unroll
    for (int i = 0; i < 4; i++) {
        int d = m_blk + ty * 4 + i;
        float ik = g_invk[d];
#pragma unroll
        for (int j = 0; j < 8; j++) {
            float v = acc[i][j] * ik * iq[j];
            atomicMax(&sm[tx * 8 + j], pack_max(v, d));
        }
    }
    __syncthreads();
    if (ty == 0) {
#pragma unroll
        for (int j = 0; j < 8; j++)
            atomicMax(&g_best[n_blk + tx * 8 + j], sm[tx * 8 + j]);
    }
}

// ---------------- kernel 7: finalize c_t, h_t, best_mem_id ----------------
__global__ __launch_bounds__(256) void finalize_kernel(const float* __restrict__ mem_vals,
                                                       float* __restrict__ out)
{
    int b = blockIdx.x;
    int best = unpack_idx(g_best[b]);
    const float* mv = mem_vals + (size_t)best * Hn;
    for (int j = threadIdx.x; j < Hn; j += 256) {
        float m = tanhf(mv[j]);
        float ct = g_cpre[b * Hn + j] + g_rg[b * Hn + j] * m;
        float ht = g_og[b * Hn + j] * tanhf(ct);
        out[OFF_CT + b * Hn + j] = ct;
        out[OFF_HT + b * Hn + j] = ht;
    }
    if (threadIdx.x == 0) out[OFF_BEST + b] = (float)best;
}

// ---------------- kernel 8: ha = relu(ct @ Wa + ba), k-split partials ----------------
__global__ __launch_bounds__(256) void gemm_ha_kernel(const float* __restrict__ A,
                                                      const float* __restrict__ Bw)
{
    __shared__ float As[2][16][64];
    __shared__ float Bs[2][16][64];
    int tid = threadIdx.x, tx = tid & 15, ty = tid >> 4;
    int m_blk = blockIdx.y * 64, n_blk = blockIdx.x * 64, kz = blockIdx.z;
    int ar = tid >> 2, akk = (tid & 3) * 4;
    int br = tid >> 4, bcc = (tid & 15) * 4;
    int kbeg = kz * 256;

    float4 sa, sb;
    auto load_stage = [&](int t) {
        int k0 = kbeg + t * 16;
        sa = *reinterpret_cast<const float4*>(&A[(m_blk + ar) * Hn + k0 + akk]);
        sb = *reinterpret_cast<const float4*>(&Bw[(k0 + br) * A2CH + n_blk + bcc]);
    };
    auto store_stage = [&](int buf) {
        As[buf][akk + 0][ar] = sa.x; As[buf][akk + 1][ar] = sa.y;
        As[buf][akk + 2][ar] = sa.z; As[buf][akk + 3][ar] = sa.w;
        *reinterpret_cast<float4*>(&Bs[buf][br][bcc]) = sb;
    };

    float acc[4][4];
#pragma unroll
    for (int i = 0; i < 4; i++)
#pragma unroll
        for (int j = 0; j < 4; j++) acc[i][j] = 0.f;

    load_stage(0); store_stage(0); __syncthreads();
    const int T = 16;
    for (int t = 0; t < T; t++) {
        int cur = t & 1;
        if (t + 1 < T) load_stage(t + 1);
#pragma unroll
        for (int k = 0; k < 16; k++) {
            float4 a4 = *reinterpret_cast<const float4*>(&As[cur][k][ty * 4]);
            float4 b4 = *reinterpret_cast<const float4*>(&Bs[cur][k][tx * 4]);
            float a[4]  = {a4.x, a4.y, a4.z, a4.w};
            float bv[4] = {b4.x, b4.y, b4.z, b4.w};
#pragma unroll
            for (int i = 0; i < 4; i++)
#pragma unroll
                for (int j = 0; j < 4; j++) acc[i][j] = fmaf(a[i], bv[j], acc[i][j]);
        }
        if (t + 1 < T) { store_stage(cur ^ 1); __syncthreads(); }
    }
    float* C = g_ha_part + kz * (Bn * A2CH);
#pragma unroll
    for (int i = 0; i < 4; i++)
#pragma unroll
        for (int j = 0; j < 4; j++)
            C[(m_blk + ty * 4 + i) * A2CH + n_blk + tx * 4 + j] = acc[i][j];
}

__global__ __launch_bounds__(256) void relu_ha_kernel(const float* __restrict__ ba)
{
    int idx = blockIdx.x * 256 + threadIdx.x;   // 131072
    float s = g_ha_part[idx] + g_ha_part[131072 + idx] + g_ha_part[262144 + idx]
            + g_ha_part[393216 + idx] + ba[idx & 511];
    g_ha[idx] = fmaxf(s, 0.f);
}

// ---------------- kernel 9: logits partials ----------------
__global__ __launch_bounds__(256) void gemm_logits_kernel(const float* __restrict__ Bw)
{
    __shared__ float As[2][16][64];
    __shared__ float Bs[2][16][64];
    int tid = threadIdx.x, tx = tid & 15, ty = tid >> 4;
    int m_blk = blockIdx.y * 64, n_blk = blockIdx.x * 64, kz = blockIdx.z;
    int ar = tid >> 2, akk = (tid & 3) * 4;
    int br = tid >> 4, bcc = (tid & 15) * 4;
    int kbeg = kz * 256;

    float4 sa, sb;
    auto load_stage = [&](int t) {
        int k0 = kbeg + t * 16;
        sa = *reinterpret_cast<const float4*>(&g_ha[(m_blk + ar) * A2CH + k0 + akk]);
        sb = *reinterpret_cast<const float4*>(&Bw[(k0 + br) * NACT + n_blk + bcc]);
    };
    auto store_stage = [&](int buf) {
        As[buf][akk + 0][ar] = sa.x; As[buf][akk + 1][ar] = sa.y;
        As[buf][akk + 2][ar] = sa.z; As[buf][akk + 3][ar] = sa.w;
        *reinterpret_cast<float4*>(&Bs[buf][br][bcc]) = sb;
    };

    float acc[4][4];
#pragma unroll
    for (int i = 0; i < 4; i++)
#pragma unroll
        for (int j = 0; j < 4; j++) acc[i][j] = 0.f;

    load_stage(0); store_stage(0); __syncthreads();
    const int T = 16;
    for (int t = 0; t < T; t++) {
        int cur = t & 1;
        if (t + 1 < T) load_stage(t + 1);
#pragma unroll
        for (int k = 0; k < 16; k++) {
            float4 a4 = *reinterpret_cast<const float4*>(&As[cur][k][ty * 4]);
            float4 b4 = *reinterpret_cast<const float4*>(&Bs[cur][k][tx * 4]);
            float a[4]  = {a4.x, a4.y, a4.z, a4.w};
            float bv[4] = {b4.x, b4.y, b4.z, b4.w};
#pragma unroll
            for (int i = 0; i < 4; i++)
#pragma unroll
                for (int j = 0; j < 4; j++) acc[i][j] = fmaf(a[i], bv[j], acc[i][j]);
        }
        if (t + 1 < T) { store_stage(cur ^ 1); __syncthreads(); }
    }
    float* C = g_logit_part + kz * (Bn * NACT);
#pragma unroll
    for (int i = 0; i < 4; i++)
#pragma unroll
        for (int j = 0; j < 4; j++)
            C[(m_blk + ty * 4 + i) * NACT + n_blk + tx * 4 + j] = acc[i][j];
}

// ---------------- kernel 10: softmax / entropy / categorical / value head ----------------
__global__ __launch_bounds__(256) void head_kernel(const float* __restrict__ b_actor,
                                                   const float* __restrict__ Wc,
                                                   const float* __restrict__ bc,
                                                   float* __restrict__ out)
{
    int b = blockIdx.x, tid = threadIdx.x;
    __shared__ float sl[NACT];
    __shared__ float red[256];
    __shared__ unsigned long long redp[256];

    float lmax = -1e30f;
#pragma unroll
    for (int t = 0; t < 4; t++) {
        int j = tid + t * 256;
        float v = g_logit_part[b * NACT + j] + g_logit_part[Bn * NACT + b * NACT + j] + b_actor[j];
        sl[j] = v;
        lmax = fmaxf(lmax, v);
    }
    red[tid] = lmax; __syncthreads();
    for (int s = 128; s > 0; s >>= 1) { if (tid < s) red[tid] = fmaxf(red[tid], red[tid + s]); __syncthreads(); }
    float mx = red[0]; __syncthreads();

    float lsum = 0.f;
#pragma unroll
    for (int t = 0; t < 4; t++) lsum += expf(sl[tid + t * 256] - mx);
    red[tid] = lsum; __syncthreads();
    for (int s = 128; s > 0; s >>= 1) { if (tid < s) red[tid] += red[tid + s]; __syncthreads(); }
    float logZ = logf(red[0]); __syncthreads();

    float ent = 0.f;
    unsigned long long bp = 0ull;
#pragma unroll
    for (int t = 0; t < 4; t++) {
        int j = tid + t * 256;
        float lp = sl[j] - mx - logZ;
        sl[j] = lp;
        ent -= expf(lp) * lp;
        float g = gumbel_noise((unsigned)(b * NACT + j));
        unsigned long long pk = pack_max(lp + g, j);
        bp = (bp > pk) ? bp : pk;
    }
    red[tid] = ent; redp[tid] = bp; __syncthreads();
    for (int s = 128; s > 0; s >>= 1) {
        if (tid < s) {
            red[tid] += red[tid + s];
            unsigned long long o = redp[tid + s];
            if (o > redp[tid]) redp[tid] = o;
        }
        __syncthreads();
    }
    float entropy = red[0];
    unsigned long long bpf = redp[0];
    __syncthreads();

    float vv = g_ha[b * A2CH + tid] * Wc[tid] + g_ha[b * A2CH + 256 + tid] * Wc[256 + tid];
    red[tid] = vv; __syncthreads();
    for (int s = 128; s > 0; s >>= 1) { if (tid < s) red[tid] += red[tid + s]; __syncthreads(); }

    if (tid == 0) {
        int a = unpack_idx(bpf);
        out[OFF_A + b]    = (float)a;
        out[OFF_PROB + b] = sl[a];
        out[OFF_V + b]    = red[0] + bc[0];
        out[OFF_ENT + b]  = entropy;
    }
}

// ---------------- kernel 11: scatter writes (last-wins, XLA order) ----------------
__global__ __launch_bounds__(256) void scatter_kernel(const int* __restrict__ widx,
                                                      const float* __restrict__ q,
                                                      const float* __restrict__ ct,
                                                      float* __restrict__ nk,
                                                      float* __restrict__ nv)
{
    int b = blockIdx.x;
    __shared__ int win;
    if (threadIdx.x == 0) {
        int idx = widx[b];
        int w = 1;
        for (int bp = b + 1; bp < Bn; bp++)
            if (widx[bp] == idx) { w = 0; break; }
        win = w;
    }
    __syncthreads();
    if (!win) return;
    int row = widx[b];
    for (int j = threadIdx.x; j < KEYD; j += 256) {
        nk[(size_t)row * KEYD + j] = q[b * KEYD + j];
        nv[(size_t)row * Hn + j]   = ct[b * Hn + j];
    }
}

// ---------------- launch ----------------
extern "C" void kernel_launch(void* const* d_in, const int* in_sizes, int n_in,
                              void* d_out, int out_size)
{
    const float* obs      = (const float*)d_in[0];
    const float* barcode  = (const float*)d_in[1];
    const float* hin      = (const float*)d_in[2];
    const float* cin      = (const float*)d_in[3];
    const int*   widx     = (const int*)d_in[4];
    const float* Wi       = (const float*)d_in[5];
    const float* bi       = (const float*)d_in[6];
    const float* Wh       = (const float*)d_in[7];
    const float* bh       = (const float*)d_in[8];
    const float* mem_keys = (const float*)d_in[9];
    const float* mem_vals = (const float*)d_in[10];
    const float* Wa       = (const float*)d_in[11];
    const float* ba       = (const float*)d_in[12];
    const float* W_actor  = (const float*)d_in[13];
    const float* b_actor  = (const float*)d_in[14];
    const float* W_critic = (const float*)d_in[15];
    const float* b_critic = (const float*)d_in[16];
    float* out = (float*)d_out;

    gemm1_kernel<<<dim3(40, 4), 256>>>(obs, hin, Wi, Wh, bi, bh);
    keys_norm_copy<<<2048, 256>>>((const float4*)mem_keys, (float4*)(out + OFF_NK));
    copy_vals<<<16384, 256>>>((const float4*)mem_vals, (float4*)(out + OFF_NV));
    qnorm_init<<<32, 256>>>((const float4*)barcode);
    gates_kernel<<<1024, 256>>>(cin);
    sims_kernel<<<dim3(256, 2), 256>>>(mem_keys, barcode);
    finalize_kernel<<<256, 256>>>(mem_vals, out);
    gemm_ha_kernel<<<dim3(8, 4, 4), 256>>>(out + OFF_CT, Wa);
    relu_ha_kernel<<<512, 256>>>(ba);
    gemm_logits_kernel<<<dim3(16, 4, 2), 256>>>(W_actor);
    head_kernel<<<256, 256>>>(b_actor, W_critic, b_critic, out);
    scatter_kernel<<<256, 256>>>(widx, barcode, out + OFF_CT, out + OFF_NK, out + OFF_NV);
}